// round 16
// baseline (speedup 1.0000x reference)
#include <cuda_runtime.h>
#include <cuda_fp16.h>
#include <cstdint>

// Problem dims
#define M_TOTAL 8192
#define K_TOTAL 4096
#define N_TOTAL 11008

// GEMM tiling: CTA 128x128x64, 4 warps (2M x 2N), warp tile 64x64
#define TILE_M 128
#define TILE_N 128
#define TILE_K 64
#define STAGES 3
#define NUM_KT (K_TOTAL / TILE_K)     // 64
#define NT_TILES (N_TOTAL / TILE_N)   // 86
#define MT_TILES (M_TOTAL / TILE_M)   // 64
#define THREADS 128

#define A_STAGE_BYTES (TILE_M * TILE_K * 2)   // 16384
#define B_STAGE_BYTES (TILE_N * TILE_K * 2)   // 16384
#define STAGE_BYTES (A_STAGE_BYTES + B_STAGE_BYTES)   // 32768
#define SMEM_BYTES (STAGES * STAGE_BYTES)             // 98304 -> 2 CTAs/SM

// fp16 scratch (device globals: allocation-free scratch)
__device__ __align__(16) __half g_a[(size_t)M_TOTAL * K_TOTAL];   // 67 MB
__device__ __align__(16) __half g_w[(size_t)N_TOTAL * K_TOTAL];   // 90 MB

// ---------------- helpers ----------------

__device__ __forceinline__ uint32_t smem_u32(const void* p) {
    uint32_t a;
    asm("{ .reg .u64 t; cvta.to.shared.u64 t, %1; cvt.u32.u64 %0, t; }"
        : "=r"(a) : "l"(p));
    return a;
}

__device__ __forceinline__ uint32_t sw128(uint32_t off) {
    return off ^ ((off >> 3) & 0x70);
}

__device__ __forceinline__ void cp16(uint32_t dst, const void* src) {
    asm volatile("cp.async.cg.shared.global [%0], [%1], 16;"
                 :: "r"(dst), "l"(src) : "memory");
}

__device__ __forceinline__ void ldm_x4(uint32_t& r0, uint32_t& r1,
                                       uint32_t& r2, uint32_t& r3, uint32_t addr) {
    asm volatile("ldmatrix.sync.aligned.m8n8.x4.shared.b16 {%0,%1,%2,%3}, [%4];"
                 : "=r"(r0), "=r"(r1), "=r"(r2), "=r"(r3) : "r"(addr));
}

__device__ __forceinline__ void mma16816(float* c, const uint32_t* a, const uint32_t* b) {
    asm volatile(
        "mma.sync.aligned.m16n8k16.row.col.f32.f16.f16.f32 "
        "{%0,%1,%2,%3}, {%4,%5,%6,%7}, {%8,%9}, {%0,%1,%2,%3};"
        : "+f"(c[0]), "+f"(c[1]), "+f"(c[2]), "+f"(c[3])
        : "r"(a[0]), "r"(a[1]), "r"(a[2]), "r"(a[3]), "r"(b[0]), "r"(b[1]));
}

// ---------------- Fused conversion kernel (one launch) ----------------

__device__ __forceinline__ uint32_t pack2f(float x, float y) {
    __half2 h = __floats2half2_rn(x, y);
    return *reinterpret_cast<uint32_t*>(&h);
}
__device__ __forceinline__ uint32_t pack2i(int x, int y) {
    __half2 h = __halves2half2(__int2half_rn(x), __int2half_rn(y));
    return *reinterpret_cast<uint32_t*>(&h);
}

#define NA_CHUNKS (M_TOTAL * K_TOTAL / 8)                 // 4,194,304 (8 floats/thread)
#define NW_CHUNKS ((size_t)N_TOTAL * K_TOTAL / 8)         // 5,636,096 (8 ints/thread)
#define CONV_BLOCKS ((NA_CHUNKS + (int)NW_CHUNKS + 255) / 256)

__global__ void convert_all_k(const float4* __restrict__ inA, uint4* __restrict__ outA,
                              const int4* __restrict__ inW, uint4* __restrict__ outW) {
    int i = blockIdx.x * blockDim.x + threadIdx.x;
    if (i < NA_CHUNKS) {
        float4 a = inA[2 * i], b = inA[2 * i + 1];
        uint4 o;
        o.x = pack2f(a.x, a.y); o.y = pack2f(a.z, a.w);
        o.z = pack2f(b.x, b.y); o.w = pack2f(b.z, b.w);
        outA[i] = o;
    } else {
        size_t j = (size_t)i - NA_CHUNKS;
        if (j < NW_CHUNKS) {
            int4 a = inW[2 * j], b = inW[2 * j + 1];
            uint4 o;
            o.x = pack2i(a.x, a.y); o.y = pack2i(a.z, a.w);
            o.z = pack2i(b.x, b.y); o.w = pack2i(b.z, b.w);
            outW[j] = o;
        }
    }
}

// ---------------- GEMM kernel ----------------
// 128 threads = 4 warps (2M x 2N), warp tile 64x64.
// Fully software-pipelined; cp.async issued in quarters smeared across the ks
// loop; ks=3's MMAs split 3:1 around the tail sync (24 pre / 8 post).

// One quarter of a stage: 2 A-chunks + 2 B-chunks per thread (4 cp.async).
__device__ __forceinline__ void load_stage_q(uint32_t sb, int stage, int kt, int q,
                                             const __half* gA, const __half* gB, int tid) {
    uint32_t sA = sb + stage * STAGE_BYTES;
    uint32_t sB = sA + A_STAGE_BYTES;
    const __half* pa = gA + kt * TILE_K;
    const __half* pb = gB + kt * TILE_K;
    #pragma unroll
    for (int i = 2 * q; i < 2 * q + 2; i++) {
        int idx = tid + i * THREADS;
        int row = idx >> 3, c = idx & 7;
        cp16(sA + sw128((uint32_t)(row * 128 + c * 16)),
             pa + (size_t)row * K_TOTAL + c * 8);
    }
    #pragma unroll
    for (int i = 2 * q; i < 2 * q + 2; i++) {
        int idx = tid + i * THREADS;
        int row = idx >> 3, c = idx & 7;
        cp16(sB + sw128((uint32_t)(row * 128 + c * 16)),
             pb + (size_t)row * K_TOTAL + c * 8);
    }
}

__device__ __forceinline__ void load_stage(uint32_t sb, int stage, int kt,
                                           const __half* gA, const __half* gB, int tid) {
    #pragma unroll
    for (int q = 0; q < 4; q++) load_stage_q(sb, stage, kt, q, gA, gB, tid);
}

__global__ void __launch_bounds__(THREADS, 2)
qlinear_gemm(const float* __restrict__ wscale,
             const float* __restrict__ wbias,
             float* __restrict__ out) {
    extern __shared__ char smem[];
    const uint32_t sb = smem_u32(smem);
    const int tid = threadIdx.x;
    const int wid = tid >> 5;
    const int lid = tid & 31;
    const int warpM = wid & 1;   // 0..1 -> M offset warpM*64
    const int warpN = wid >> 1;  // 0..1 -> N offset warpN*64

    // M fastest: W panel (1 MB) + all of A stay L2-hot
    const int mt = blockIdx.x % MT_TILES;
    const int nt = blockIdx.x / MT_TILES;
    const int m0 = mt * TILE_M;
    const int n0 = nt * TILE_N;

    const __half* gA = g_a + (size_t)m0 * K_TOTAL;
    const __half* gB = g_w + (size_t)n0 * K_TOTAL;

    float acc[4][8][4];
    #pragma unroll
    for (int i = 0; i < 4; i++)
        #pragma unroll
        for (int j = 0; j < 8; j++)
            #pragma unroll
            for (int v = 0; v < 4; v++) acc[i][j][v] = 0.0f;

    // ldmatrix lane addressing
    const int a_row = warpM * 64 + (lid & 15);
    const int a_kb  = ((lid >> 4) & 1) * 16;
    const int b_row = warpN * 64 + ((lid >> 4) & 1) * 8 + (lid & 7);
    const int b_kb  = ((lid >> 3) & 1) * 16;

    // Double-buffered fragments
    uint32_t afr[2][4][4];   // [buf][mi][reg]
    uint32_t bfr[2][8][2];   // [buf][ni][reg]

    #define PREFETCH_FRAGS(BUF, SA, SB_, KS)                                          \
        do {                                                                          \
            _Pragma("unroll")                                                         \
            for (int mi = 0; mi < 4; mi++) {                                          \
                uint32_t off = (uint32_t)((a_row + mi * 16) * 128 + (KS) * 32 + a_kb);\
                ldm_x4(afr[BUF][mi][0], afr[BUF][mi][1],                              \
                       afr[BUF][mi][2], afr[BUF][mi][3], (SA) + sw128(off));          \
            }                                                                         \
            _Pragma("unroll")                                                         \
            for (int bj = 0; bj < 4; bj++) {                                          \
                uint32_t t0, t1, t2, t3;                                              \
                uint32_t off = (uint32_t)((b_row + bj * 16) * 128 + (KS) * 32 + b_kb);\
                ldm_x4(t0, t1, t2, t3, (SB_) + sw128(off));                           \
                bfr[BUF][bj * 2][0] = t0;     bfr[BUF][bj * 2][1] = t1;               \
                bfr[BUF][bj * 2 + 1][0] = t2; bfr[BUF][bj * 2 + 1][1] = t3;           \
            }                                                                         \
        } while (0)

    #define MMA_ALL(BUF)                                                              \
        do {                                                                          \
            _Pragma("unroll")                                                         \
            for (int mi = 0; mi < 4; mi++)                                            \
                _Pragma("unroll")                                                     \
                for (int ni = 0; ni < 8; ni++)                                        \
                    mma16816(acc[mi][ni], afr[BUF][mi], bfr[BUF][ni]);                \
        } while (0)

    // Part of ks=3's MMAs (mi = MLO..MHI), registers only
    #define MMA_PART(BUF, MLO, MHI)                                                   \
        do {                                                                          \
            _Pragma("unroll")                                                         \
            for (int mi = (MLO); mi <= (MHI); mi++)                                   \
                _Pragma("unroll")                                                     \
                for (int ni = 0; ni < 8; ni++)                                        \
                    mma16816(acc[mi][ni], afr[BUF][mi], bfr[BUF][ni]);                \
        } while (0)

    // Prologue: stages 0,1 in flight; stage 0 visible; ks=0 frags in buf 0.
    load_stage(sb, 0, 0, gA, gB, tid);
    asm volatile("cp.async.commit_group;" ::: "memory");
    load_stage(sb, 1, 1, gA, gB, tid);
    asm volatile("cp.async.commit_group;" ::: "memory");
    asm volatile("cp.async.wait_group 1;" ::: "memory");   // own stage-0 groups done
    __syncthreads();                                        // stage 0 CTA-visible
    {
        const uint32_t sA0 = sb;
        const uint32_t sB0 = sA0 + A_STAGE_BYTES;
        PREFETCH_FRAGS(0, sA0, sB0, 0);
    }

    for (int kt = 0; kt < NUM_KT; kt++) {
        const uint32_t sA = sb + (kt % STAGES) * STAGE_BYTES;
        const uint32_t sB = sA + A_STAGE_BYTES;

        // Stage kt+2 loads are smeared through the ks loop in quarters; slot
        // (kt+2)%3 was last read at iter kt-1 (ordered by the kt-1 tail barrier).
        const bool do_load = (kt + 2 < NUM_KT);
        const int nstage = (kt + 2) % STAGES;

        // ks = 0..2: one load quarter + prefetch ks+1 frags + MMA ks
        #pragma unroll
        for (int ks = 0; ks < 3; ks++) {
            const int cur = ks & 1;
            const int nxt = cur ^ 1;
            if (do_load) load_stage_q(sb, nstage, kt + 2, ks, gA, gB, tid);
            PREFETCH_FRAGS(nxt, sA, sB, ks + 1);
            MMA_ALL(cur);
        }

        // Final load quarter, then commit (all 16 cp.asyncs of stage kt+2 in group)
        if (do_load) load_stage_q(sb, nstage, kt + 2, 3, gA, gB, tid);
        asm volatile("cp.async.commit_group;" ::: "memory");

        // ks = 3, first 3/4 (24 MMAs, registers only): queue tensor work that
        // drains WHILE this warp stalls at the wait/barrier below (with 2 warps
        // per SMSP this is ~384 cyc of pipe cover).
        MMA_PART(1, 0, 2);

        // Tail: publish stage kt+1, prefetch its ks=0 under ks=3's last quarter.
        if (kt + 1 < NUM_KT) {
            asm volatile("cp.async.wait_group 1;" ::: "memory"); // own kt+1 groups done
            __syncthreads();  // (a) all threads' stage-kt+1 data visible
                              // (b) WAR: slot-kt reads (all above) before next writes
            const uint32_t sA1 = sb + ((kt + 1) % STAGES) * STAGE_BYTES;
            const uint32_t sB1 = sA1 + A_STAGE_BYTES;
            PREFETCH_FRAGS(0, sA1, sB1, 0);   // overlaps ks=3 last quarter below
        }
        MMA_PART(1, 3, 3);   // ks = 3, last quarter (registers only)
    }

    #undef PREFETCH_FRAGS
    #undef MMA_ALL
    #undef MMA_PART

    // Epilogue: direct STG with per-column scale + bias
    #pragma unroll
    for (int ni = 0; ni < 8; ni++) {
        const int col = n0 + warpN * 64 + ni * 8 + (lid & 3) * 2;
        const float2 s = *reinterpret_cast<const float2*>(wscale + col);
        const float2 b = *reinterpret_cast<const float2*>(wbias + col);
        #pragma unroll
        for (int mi = 0; mi < 4; mi++) {
            const int row = m0 + warpM * 64 + mi * 16 + (lid >> 2);
            float2 v0, v1;
            v0.x = acc[mi][ni][0] * s.x + b.x;
            v0.y = acc[mi][ni][1] * s.y + b.y;
            v1.x = acc[mi][ni][2] * s.x + b.x;
            v1.y = acc[mi][ni][3] * s.y + b.y;
            *reinterpret_cast<float2*>(out + (size_t)row * N_TOTAL + col) = v0;
            *reinterpret_cast<float2*>(out + (size_t)(row + 8) * N_TOTAL + col) = v1;
        }
    }
}

// ---------------- Launch ----------------

extern "C" void kernel_launch(void* const* d_in, const int* in_sizes, int n_in,
                              void* d_out, int out_size) {
    const float* input  = (const float*)d_in[0];   // [8192, 4096] fp32
    const int*   qw     = (const int*)d_in[1];     // [11008, 4096] int32 in {0,1,2}
    const float* wscale = (const float*)d_in[2];   // [11008]
    const float* wbias  = (const float*)d_in[3];   // [11008]
    float* out = (float*)d_out;                    // [8192, 11008] fp32

    void* pa = nullptr;
    void* pw = nullptr;
    cudaGetSymbolAddress(&pa, g_a);
    cudaGetSymbolAddress(&pw, g_w);

    convert_all_k<<<CONV_BLOCKS, 256>>>((const float4*)input, (uint4*)pa,
                                        (const int4*)qw, (uint4*)pw);

    cudaFuncSetAttribute(qlinear_gemm,
                         cudaFuncAttributeMaxDynamicSharedMemorySize, SMEM_BYTES);
    qlinear_gemm<<<MT_TILES * NT_TILES, THREADS, SMEM_BYTES>>>(wscale, wbias, out);
}

// round 17
// speedup vs baseline: 1.0061x; 1.0061x over previous
#include <cuda_runtime.h>
#include <cuda_fp16.h>
#include <cstdint>

// Problem dims
#define M_TOTAL 8192
#define K_TOTAL 4096
#define N_TOTAL 11008

// GEMM tiling: CTA 128x128x64, 4 warps (2M x 2N), warp tile 64x64
#define TILE_M 128
#define TILE_N 128
#define TILE_K 64
#define STAGES 3
#define NUM_KT (K_TOTAL / TILE_K)     // 64
#define NT_TILES (N_TOTAL / TILE_N)   // 86
#define MT_TILES (M_TOTAL / TILE_M)   // 64
#define THREADS 128

#define A_STAGE_BYTES (TILE_M * TILE_K * 2)   // 16384
#define B_STAGE_BYTES (TILE_N * TILE_K * 2)   // 16384
#define STAGE_BYTES (A_STAGE_BYTES + B_STAGE_BYTES)   // 32768
#define SMEM_BYTES (STAGES * STAGE_BYTES)             // 98304 -> 2 CTAs/SM

// fp16 scratch (device globals: allocation-free scratch)
__device__ __align__(16) __half g_a[(size_t)M_TOTAL * K_TOTAL];   // 67 MB
__device__ __align__(16) __half g_w[(size_t)N_TOTAL * K_TOTAL];   // 90 MB

// ---------------- helpers ----------------

__device__ __forceinline__ uint32_t smem_u32(const void* p) {
    uint32_t a;
    asm("{ .reg .u64 t; cvta.to.shared.u64 t, %1; cvt.u32.u64 %0, t; }"
        : "=r"(a) : "l"(p));
    return a;
}

__device__ __forceinline__ uint32_t sw128(uint32_t off) {
    return off ^ ((off >> 3) & 0x70);
}

__device__ __forceinline__ void cp16(uint32_t dst, const void* src) {
    asm volatile("cp.async.cg.shared.global [%0], [%1], 16;"
                 :: "r"(dst), "l"(src) : "memory");
}

__device__ __forceinline__ void ldm_x4(uint32_t& r0, uint32_t& r1,
                                       uint32_t& r2, uint32_t& r3, uint32_t addr) {
    asm volatile("ldmatrix.sync.aligned.m8n8.x4.shared.b16 {%0,%1,%2,%3}, [%4];"
                 : "=r"(r0), "=r"(r1), "=r"(r2), "=r"(r3) : "r"(addr));
}

__device__ __forceinline__ void mma16816(float* c, const uint32_t* a, const uint32_t* b) {
    asm volatile(
        "mma.sync.aligned.m16n8k16.row.col.f32.f16.f16.f32 "
        "{%0,%1,%2,%3}, {%4,%5,%6,%7}, {%8,%9}, {%0,%1,%2,%3};"
        : "+f"(c[0]), "+f"(c[1]), "+f"(c[2]), "+f"(c[3])
        : "r"(a[0]), "r"(a[1]), "r"(a[2]), "r"(a[3]), "r"(b[0]), "r"(b[1]));
}

// ---------------- Fused conversion kernel (one launch) ----------------

__device__ __forceinline__ uint32_t pack2f(float x, float y) {
    __half2 h = __floats2half2_rn(x, y);
    return *reinterpret_cast<uint32_t*>(&h);
}
__device__ __forceinline__ uint32_t pack2i(int x, int y) {
    __half2 h = __halves2half2(__int2half_rn(x), __int2half_rn(y));
    return *reinterpret_cast<uint32_t*>(&h);
}

#define NA_CHUNKS (M_TOTAL * K_TOTAL / 8)                 // 4,194,304 (8 floats/thread)
#define NW_CHUNKS ((size_t)N_TOTAL * K_TOTAL / 8)         // 5,636,096 (8 ints/thread)
#define CONV_BLOCKS ((NA_CHUNKS + (int)NW_CHUNKS + 255) / 256)

__global__ void convert_all_k(const float4* __restrict__ inA, uint4* __restrict__ outA,
                              const int4* __restrict__ inW, uint4* __restrict__ outW) {
    int i = blockIdx.x * blockDim.x + threadIdx.x;
    if (i < NA_CHUNKS) {
        float4 a = inA[2 * i], b = inA[2 * i + 1];
        uint4 o;
        o.x = pack2f(a.x, a.y); o.y = pack2f(a.z, a.w);
        o.z = pack2f(b.x, b.y); o.w = pack2f(b.z, b.w);
        outA[i] = o;
    } else {
        size_t j = (size_t)i - NA_CHUNKS;
        if (j < NW_CHUNKS) {
            int4 a = inW[2 * j], b = inW[2 * j + 1];
            uint4 o;
            o.x = pack2i(a.x, a.y); o.y = pack2i(a.z, a.w);
            o.z = pack2i(b.x, b.y); o.w = pack2i(b.z, b.w);
            outW[j] = o;
        }
    }
}

// ---------------- GEMM kernel ----------------
// 128 threads = 4 warps (2M x 2N), warp tile 64x64.
// Fully software-pipelined; cp.async issued in quarters smeared across the ks
// loop; ks=3's MMAs split 2:2 around the tail sync, with the post-barrier half
// issued BEFORE the next-stage fragment prefetch (tensor pipe refills first).

// One quarter of a stage: 2 A-chunks + 2 B-chunks per thread (4 cp.async).
__device__ __forceinline__ void load_stage_q(uint32_t sb, int stage, int kt, int q,
                                             const __half* gA, const __half* gB, int tid) {
    uint32_t sA = sb + stage * STAGE_BYTES;
    uint32_t sB = sA + A_STAGE_BYTES;
    const __half* pa = gA + kt * TILE_K;
    const __half* pb = gB + kt * TILE_K;
    #pragma unroll
    for (int i = 2 * q; i < 2 * q + 2; i++) {
        int idx = tid + i * THREADS;
        int row = idx >> 3, c = idx & 7;
        cp16(sA + sw128((uint32_t)(row * 128 + c * 16)),
             pa + (size_t)row * K_TOTAL + c * 8);
    }
    #pragma unroll
    for (int i = 2 * q; i < 2 * q + 2; i++) {
        int idx = tid + i * THREADS;
        int row = idx >> 3, c = idx & 7;
        cp16(sB + sw128((uint32_t)(row * 128 + c * 16)),
             pb + (size_t)row * K_TOTAL + c * 8);
    }
}

__device__ __forceinline__ void load_stage(uint32_t sb, int stage, int kt,
                                           const __half* gA, const __half* gB, int tid) {
    #pragma unroll
    for (int q = 0; q < 4; q++) load_stage_q(sb, stage, kt, q, gA, gB, tid);
}

__global__ void __launch_bounds__(THREADS, 2)
qlinear_gemm(const float* __restrict__ wscale,
             const float* __restrict__ wbias,
             float* __restrict__ out) {
    extern __shared__ char smem[];
    const uint32_t sb = smem_u32(smem);
    const int tid = threadIdx.x;
    const int wid = tid >> 5;
    const int lid = tid & 31;
    const int warpM = wid & 1;   // 0..1 -> M offset warpM*64
    const int warpN = wid >> 1;  // 0..1 -> N offset warpN*64

    // M fastest: W panel (1 MB) + all of A stay L2-hot
    const int mt = blockIdx.x % MT_TILES;
    const int nt = blockIdx.x / MT_TILES;
    const int m0 = mt * TILE_M;
    const int n0 = nt * TILE_N;

    const __half* gA = g_a + (size_t)m0 * K_TOTAL;
    const __half* gB = g_w + (size_t)n0 * K_TOTAL;

    float acc[4][8][4];
    #pragma unroll
    for (int i = 0; i < 4; i++)
        #pragma unroll
        for (int j = 0; j < 8; j++)
            #pragma unroll
            for (int v = 0; v < 4; v++) acc[i][j][v] = 0.0f;

    // ldmatrix lane addressing
    const int a_row = warpM * 64 + (lid & 15);
    const int a_kb  = ((lid >> 4) & 1) * 16;
    const int b_row = warpN * 64 + ((lid >> 4) & 1) * 8 + (lid & 7);
    const int b_kb  = ((lid >> 3) & 1) * 16;

    // Double-buffered fragments
    uint32_t afr[2][4][4];   // [buf][mi][reg]
    uint32_t bfr[2][8][2];   // [buf][ni][reg]

    #define PREFETCH_FRAGS(BUF, SA, SB_, KS)                                          \
        do {                                                                          \
            _Pragma("unroll")                                                         \
            for (int mi = 0; mi < 4; mi++) {                                          \
                uint32_t off = (uint32_t)((a_row + mi * 16) * 128 + (KS) * 32 + a_kb);\
                ldm_x4(afr[BUF][mi][0], afr[BUF][mi][1],                              \
                       afr[BUF][mi][2], afr[BUF][mi][3], (SA) + sw128(off));          \
            }                                                                         \
            _Pragma("unroll")                                                         \
            for (int bj = 0; bj < 4; bj++) {                                          \
                uint32_t t0, t1, t2, t3;                                              \
                uint32_t off = (uint32_t)((b_row + bj * 16) * 128 + (KS) * 32 + b_kb);\
                ldm_x4(t0, t1, t2, t3, (SB_) + sw128(off));                           \
                bfr[BUF][bj * 2][0] = t0;     bfr[BUF][bj * 2][1] = t1;               \
                bfr[BUF][bj * 2 + 1][0] = t2; bfr[BUF][bj * 2 + 1][1] = t3;           \
            }                                                                         \
        } while (0)

    #define MMA_ALL(BUF)                                                              \
        do {                                                                          \
            _Pragma("unroll")                                                         \
            for (int mi = 0; mi < 4; mi++)                                            \
                _Pragma("unroll")                                                     \
                for (int ni = 0; ni < 8; ni++)                                        \
                    mma16816(acc[mi][ni], afr[BUF][mi], bfr[BUF][ni]);                \
        } while (0)

    // Half of ks=3's MMAs (mi = MLO..MHI), registers only
    #define MMA_HALF(BUF, MLO, MHI)                                                   \
        do {                                                                          \
            _Pragma("unroll")                                                         \
            for (int mi = (MLO); mi <= (MHI); mi++)                                   \
                _Pragma("unroll")                                                     \
                for (int ni = 0; ni < 8; ni++)                                        \
                    mma16816(acc[mi][ni], afr[BUF][mi], bfr[BUF][ni]);                \
        } while (0)

    // Prologue: stages 0,1 in flight; stage 0 visible; ks=0 frags in buf 0.
    load_stage(sb, 0, 0, gA, gB, tid);
    asm volatile("cp.async.commit_group;" ::: "memory");
    load_stage(sb, 1, 1, gA, gB, tid);
    asm volatile("cp.async.commit_group;" ::: "memory");
    asm volatile("cp.async.wait_group 1;" ::: "memory");   // own stage-0 groups done
    __syncthreads();                                        // stage 0 CTA-visible
    {
        const uint32_t sA0 = sb;
        const uint32_t sB0 = sA0 + A_STAGE_BYTES;
        PREFETCH_FRAGS(0, sA0, sB0, 0);
    }

    for (int kt = 0; kt < NUM_KT; kt++) {
        const uint32_t sA = sb + (kt % STAGES) * STAGE_BYTES;
        const uint32_t sB = sA + A_STAGE_BYTES;

        // Stage kt+2 loads are smeared through the ks loop in quarters; slot
        // (kt+2)%3 was last read at iter kt-1 (ordered by the kt-1 tail barrier).
        const bool do_load = (kt + 2 < NUM_KT);
        const int nstage = (kt + 2) % STAGES;

        // ks = 0..2: one load quarter + prefetch ks+1 frags + MMA ks
        #pragma unroll
        for (int ks = 0; ks < 3; ks++) {
            const int cur = ks & 1;
            const int nxt = cur ^ 1;
            if (do_load) load_stage_q(sb, nstage, kt + 2, ks, gA, gB, tid);
            PREFETCH_FRAGS(nxt, sA, sB, ks + 1);
            MMA_ALL(cur);
        }

        // Final load quarter, then commit (all 16 cp.asyncs of stage kt+2 in group)
        if (do_load) load_stage_q(sb, nstage, kt + 2, 3, gA, gB, tid);
        asm volatile("cp.async.commit_group;" ::: "memory");

        // ks = 3, first half (16 MMAs, registers only): queue tensor work that
        // drains WHILE this warp stalls at the wait/barrier below.
        MMA_HALF(1, 0, 1);

        // Tail: publish stage kt+1. Post-barrier, issue ks=3's second half FIRST
        // (registers only -> tensor pipe refills immediately), THEN prefetch the
        // next stage's ks=0 fragments (LDSMs hide under the queued MMAs; first
        // use is after next kt's load-quarter + ks=1 prefetch).
        if (kt + 1 < NUM_KT) {
            asm volatile("cp.async.wait_group 1;" ::: "memory"); // own kt+1 groups done
            __syncthreads();  // (a) all threads' stage-kt+1 data visible
                              // (b) WAR: slot-kt reads (all above) before next writes
            MMA_HALF(1, 2, 3);   // ks = 3, second half (registers only)
            const uint32_t sA1 = sb + ((kt + 1) % STAGES) * STAGE_BYTES;
            const uint32_t sB1 = sA1 + A_STAGE_BYTES;
            PREFETCH_FRAGS(0, sA1, sB1, 0);
        } else {
            MMA_HALF(1, 2, 3);   // last iteration: just finish
        }
    }

    #undef PREFETCH_FRAGS
    #undef MMA_ALL
    #undef MMA_HALF

    // Epilogue: direct STG with per-column scale + bias
    #pragma unroll
    for (int ni = 0; ni < 8; ni++) {
        const int col = n0 + warpN * 64 + ni * 8 + (lid & 3) * 2;
        const float2 s = *reinterpret_cast<const float2*>(wscale + col);
        const float2 b = *reinterpret_cast<const float2*>(wbias + col);
        #pragma unroll
        for (int mi = 0; mi < 4; mi++) {
            const int row = m0 + warpM * 64 + mi * 16 + (lid >> 2);
            float2 v0, v1;
            v0.x = acc[mi][ni][0] * s.x + b.x;
            v0.y = acc[mi][ni][1] * s.y + b.y;
            v1.x = acc[mi][ni][2] * s.x + b.x;
            v1.y = acc[mi][ni][3] * s.y + b.y;
            *reinterpret_cast<float2*>(out + (size_t)row * N_TOTAL + col) = v0;
            *reinterpret_cast<float2*>(out + (size_t)(row + 8) * N_TOTAL + col) = v1;
        }
    }
}

// ---------------- Launch ----------------

extern "C" void kernel_launch(void* const* d_in, const int* in_sizes, int n_in,
                              void* d_out, int out_size) {
    const float* input  = (const float*)d_in[0];   // [8192, 4096] fp32
    const int*   qw     = (const int*)d_in[1];     // [11008, 4096] int32 in {0,1,2}
    const float* wscale = (const float*)d_in[2];   // [11008]
    const float* wbias  = (const float*)d_in[3];   // [11008]
    float* out = (float*)d_out;                    // [8192, 11008] fp32

    void* pa = nullptr;
    void* pw = nullptr;
    cudaGetSymbolAddress(&pa, g_a);
    cudaGetSymbolAddress(&pw, g_w);

    convert_all_k<<<CONV_BLOCKS, 256>>>((const float4*)input, (uint4*)pa,
                                        (const int4*)qw, (uint4*)pw);

    cudaFuncSetAttribute(qlinear_gemm,
                         cudaFuncAttributeMaxDynamicSharedMemorySize, SMEM_BYTES);
    qlinear_gemm<<<MT_TILES * NT_TILES, THREADS, SMEM_BYTES>>>(wscale, wbias, out);
}